// round 15
// baseline (speedup 1.0000x reference)
#include <cuda_runtime.h>

#define NB   256
#define NPTS 2000
#define M1   100
#define M2   5
#define K1   20
#define K2   20
#define F1   5
#define F2   25
#define F3   45
#define NT   512
#define FULLM 0xffffffffu

// grid: 14^3 cells of size 0.6 covering [-4.2, 4.2] (clamped outside)
#define GC    14
#define GC2   (GC*GC)
#define GCELLS (GC*GC*GC)          // 2744
#define GPAIRS ((GCELLS+1)/2)      // 1372

#define DYN_SMEM (3*2048*4)        // s_cpx/s_cpy/s_cpz

typedef unsigned long long u64;

// ---- f32x2 packed helpers (rn, bit-identical to scalar FADD/FMUL/FFMA) ----
__device__ __forceinline__ u64 pk2(float a, float b){
  u64 r; asm("mov.b64 %0, {%1,%2};" : "=l"(r) : "f"(a), "f"(b)); return r;
}
__device__ __forceinline__ void upk2(u64 v, float& a, float& b){
  asm("mov.b64 {%0,%1}, %2;" : "=f"(a), "=f"(b) : "l"(v));
}
__device__ __forceinline__ u64 add2(u64 a, u64 b){
  u64 r; asm("add.rn.f32x2 %0, %1, %2;" : "=l"(r) : "l"(a), "l"(b)); return r;
}
__device__ __forceinline__ u64 mul2(u64 a, u64 b){
  u64 r; asm("mul.rn.f32x2 %0, %1, %2;" : "=l"(r) : "l"(a), "l"(b)); return r;
}
__device__ __forceinline__ u64 fma2(u64 a, u64 b, u64 c){
  u64 r; asm("fma.rn.f32x2 %0, %1, %2, %3;" : "=l"(r) : "l"(a), "l"(b), "l"(c)); return r;
}

__device__ __forceinline__ float fmin_xor(float v){
  #pragma unroll
  for (int off = 16; off; off >>= 1)
    v = fminf(v, __shfl_xor_sync(FULLM, v, off));
  return v;
}
__device__ __forceinline__ int isum_xor(int v){
  #pragma unroll
  for (int off = 16; off; off >>= 1)
    v += __shfl_xor_sync(FULLM, v, off);
  return v;
}
__device__ __forceinline__ void argmax_xor(float& v, int& i){
  #pragma unroll
  for (int off = 16; off; off >>= 1){
    float ov = __shfl_xor_sync(FULLM, v, off);
    int   oi = __shfl_xor_sync(FULLM, i, off);
    if (ov > v || (ov == v && oi < i)) { v = ov; i = oi; }
  }
}
__device__ __forceinline__ float fredux_max_nn(float v){
  return __uint_as_float(__reduce_max_sync(FULLM, __float_as_uint(v)));
}
__device__ __forceinline__ int cellco(float x){
  int c = (int)floorf((x + 4.2f) * (1.0f/0.6f));
  return min(GC-1, max(0, c));
}

__global__ void __launch_bounds__(NT, 2)
net_kernel(const float* __restrict__ points,
           const float* __restrict__ W1, const float* __restrict__ b1,
           const float* __restrict__ W2, const float* __restrict__ b2,
           const float* __restrict__ W3, const float* __restrict__ b3,
           const float* __restrict__ D1, const float* __restrict__ bD1,
           const float* __restrict__ D2, const float* __restrict__ bD2,
           const float* __restrict__ D3, const float* __restrict__ bD3,
           float* __restrict__ out)
{
  __shared__ float s_px[NPTS], s_py[NPTS], s_pz[NPTS];   // original order (FPS ties!)
  __shared__ union {
    struct { unsigned cntc[GPAIRS];                      // packed u16 counts/cursors
             unsigned short start[GCELLS+1]; } grid;     // segment starts
    struct { float o1[140]; float cf[125]; float o2[800];
             float latent[F3]; float f2[M2][F2]; } tail;
  } s_u;
  __shared__ float4   s_samp[M1];
  __shared__ float    s_f1[M1][F1];
  __shared__ u64      s_slots[8];            // FPS per-warp tagged candidates
  __shared__ unsigned s_lastpost;            // FPS tagged winner broadcast
  __shared__ int      s_wsum[8];
  __shared__ float    s_s2x[M2], s_s2y[M2], s_s2z[M2];
  __shared__ int      s_s2i[M2];
  __shared__ float    s_W1s[15], s_b1[F1];   // W1 prescaled by 1/R1
  __shared__ float    s_W2[200], s_b2[F2];
  __shared__ int      s_prog, s_qhead, s_gridok;

  // cell-sorted coordinate copies (dynamic smem)
  extern __shared__ float s_dyn[];
  float* s_cpx = s_dyn;
  float* s_cpy = s_dyn + 2048;
  float* s_cpz = s_dyn + 4096;

  const int b = blockIdx.x, tid = threadIdx.x;
  const int lane = tid & 31, wid = tid >> 5;
  const float* P = points + (size_t)b * NPTS * 3;

  // ---- Stage 0: load cloud + small weights + sync-protocol init ----
  for (int i = tid; i < NPTS; i += NT){
    s_px[i] = P[3*i+0]; s_py[i] = P[3*i+1]; s_pz[i] = P[3*i+2];
  }
  if (tid == 0){ s_prog = 0; s_qhead = 0; s_gridok = 0; }
  if (tid >= 16 && tid < 24)         s_slots[tid-16] = 127ull;   // tag != 0
  if (tid == 24)                     s_lastpost = 127u;          // tag != 1
  if (tid >= 448 && tid < 463)       s_W1s[tid-448] = W1[tid-448] * (1.0f/0.3f);
  if (tid >= 464 && tid < 464+F1)    s_b1[tid-464]  = b1[tid-464];
  if (tid >= 64  && tid < 264)       s_W2[tid-64]   = W2[tid-64];
  if (tid >= 288 && tid < 288+F2)    s_b2[tid-288]  = b2[tid-288];
  __syncthreads();

  if (tid < 256){
    // ======== Producers: FPS level 1 (warps 0-7), barrier-free pipeline ====
    float md[8];
    u64 pxp[4], pyp[4], pzp[4];
    #pragma unroll
    for (int u2 = 0; u2 < 4; u2++){
      int ia = tid + 256*(2*u2), ib = tid + 256*(2*u2+1);
      int ja = (ia < NPTS) ? ia : 0, jb = (ib < NPTS) ? ib : 0;
      pxp[u2] = pk2(s_px[ja], s_px[jb]);
      pyp[u2] = pk2(s_py[ja], s_py[jb]);
      pzp[u2] = pk2(s_pz[ja], s_pz[jb]);
      md[2*u2]   = (ia < NPTS) ? 1e10f : -1.0f;
      md[2*u2+1] = (ib < NPTS) ? 1e10f : -1.0f;
    }
    if (tid == 0){
      s_samp[0] = make_float4(s_px[0], s_py[0], s_pz[0], 0.0f);
      __threadfence_block();
      *(volatile int*)&s_prog = 1;
    }
    int last = 0;
    for (int s = 0; s < M1-1; s++){
      if (s > 0){
        unsigned lp;
        do { lp = *(volatile unsigned*)&s_lastpost; }
        while ((lp & 127u) != (unsigned)(s & 127));
        last = (int)(lp >> 7);
      }
      float lx = s_px[last], ly = s_py[last], lz = s_pz[last];
      u64 nLx = pk2(-lx, -lx), nLy = pk2(-ly, -ly), nLz = pk2(-lz, -lz);
      float bv = -0.5f; int bi = 0;
      #pragma unroll
      for (int u2 = 0; u2 < 4; u2++){
        u64 dx = add2(pxp[u2], nLx);
        u64 dy = add2(pyp[u2], nLy);
        u64 dz = add2(pzp[u2], nLz);
        u64 dd = mul2(dx, dx);
        dd = fma2(dy, dy, dd);
        dd = fma2(dz, dz, dd);
        float d0, d1; upk2(dd, d0, d1);
        int u = 2*u2;
        md[u] = fminf(md[u], d0);
        if (md[u] > bv){ bv = md[u]; bi = tid + 256*u; }
        md[u+1] = fminf(md[u+1], d1);
        if (md[u+1] > bv){ bv = md[u+1]; bi = tid + 256*(u+1); }
      }
      // per-warp argmax (bv >= 0): max on bits, min-index tie-break
      unsigned bits = __float_as_uint(bv);
      unsigned bu = __reduce_max_sync(FULLM, bits);
      unsigned mi = __reduce_min_sync(FULLM, (bits == bu) ? (unsigned)bi : 0xFFFFFFFFu);
      if (lane == 0){
        u64 key = (((u64)bu) << 32)
                | (u64)(((2047u - mi) << 7) | (unsigned)(s & 127));
        *(volatile u64*)&s_slots[wid] = key;
      }
      if (wid == 0){
        // coordinator: wait for all 8 slots at tag s, reduce, publish
        u64 myk = 0;
        for (;;){
          u64 v = (lane < 8) ? *(volatile u64*)&s_slots[lane] : 0ull;
          bool ok = (lane >= 8) || ((unsigned)(v & 127u) == (unsigned)(s & 127));
          if (__all_sync(FULLM, ok)){ myk = v; break; }
        }
        unsigned kh = (unsigned)(myk >> 32);
        unsigned kl = (unsigned)(myk & 0xFFFFFFFFu);
        unsigned gvh = __reduce_max_sync(FULLM, (lane < 8) ? kh : 0u);
        unsigned gvl = __reduce_max_sync(FULLM, (lane < 8 && kh == gvh) ? kl : 0u);
        int nl = (int)(2047u - (gvl >> 7));
        if (lane == 0){
          s_samp[s+1] = make_float4(s_px[nl], s_py[nl], s_pz[nl], 0.0f);
          __threadfence_block();
          *(volatile int*)&s_prog = s + 2;
          *(volatile unsigned*)&s_lastpost =
              ((unsigned)nl << 7) | (unsigned)((s+1) & 127);
        }
      }
    }
    __syncwarp();
    // ---- FPS level 2 (100 -> 5): warp 0 only ----
    if (wid == 0){
      float m[4];
      #pragma unroll
      for (int u = 0; u < 4; u++) m[u] = 1e10f;
      int last2 = 0;
      for (int s = 0; s < M2; s++){
        if (lane == 0) s_s2i[s] = last2;
        const float4 L = s_samp[last2];
        float bv = -1.0f; int bi = 0;
        #pragma unroll
        for (int u = 0; u < 4; u++){
          int i = lane + 32*u;
          if (i < M1){
            float4 p = s_samp[i];
            float dx = p.x-L.x, dy = p.y-L.y, dz = p.z-L.z;
            float d  = dx*dx + dy*dy + dz*dz;
            if (d < m[u]) m[u] = d;
            if (m[u] > bv){ bv = m[u]; bi = i; }
          }
        }
        argmax_xor(bv, bi);
        last2 = __shfl_sync(FULLM, bi, 0);
      }
      __syncwarp();
      if (lane < M2){
        float4 p = s_samp[s_s2i[lane]];
        s_s2x[lane] = p.x; s_s2y[lane] = p.y; s_s2z[lane] = p.z;
      }
    }
  } else {
    // ======== Consumers (warps 8-15): build spatial grid ========
    const int ctid = tid - 256;
    const int cw = ctid >> 5;
    for (int p = ctid; p < GPAIRS; p += 256) s_u.grid.cntc[p] = 0;
    asm volatile("bar.sync 2, 256;" ::: "memory");
    // count
    for (int i = ctid; i < NPTS; i += 256){
      int c = (cellco(s_pz[i])*GC + cellco(s_py[i]))*GC + cellco(s_px[i]);
      atomicAdd(&s_u.grid.cntc[c>>1], (c&1) ? 0x10000u : 1u);
    }
    asm volatile("bar.sync 2, 256;" ::: "memory");
    // prefix sum (each thread owns 11 cells)
    {
      int base = ctid * 11;
      int lc[11]; int sum = 0;
      #pragma unroll
      for (int k = 0; k < 11; k++){
        int c = base + k;
        int v = (c < GCELLS) ? (int)((s_u.grid.cntc[c>>1] >> ((c&1)*16)) & 0xFFFFu) : 0;
        lc[k] = v; sum += v;
      }
      int incl = sum;
      #pragma unroll
      for (int o = 1; o < 32; o <<= 1){
        int n = __shfl_up_sync(FULLM, incl, o);
        if (lane >= o) incl += n;
      }
      if (lane == 31) s_wsum[cw] = incl;
      asm volatile("bar.sync 2, 256;" ::: "memory");
      int woff = 0;
      #pragma unroll
      for (int w = 0; w < 8; w++) woff += (w < cw) ? s_wsum[w] : 0;
      int run = woff + incl - sum;
      #pragma unroll
      for (int k = 0; k < 11; k++){
        int c = base + k;
        if (c <= GCELLS) s_u.grid.start[c] = (unsigned short)run;
        run += lc[k];
      }
    }
    asm volatile("bar.sync 2, 256;" ::: "memory");
    // cursors = copy of starts (reuse cntc)
    for (int p = ctid; p < GPAIRS; p += 256){
      unsigned lo = s_u.grid.start[2*p];
      unsigned hi = s_u.grid.start[2*p+1];
      s_u.grid.cntc[p] = lo | (hi << 16);
    }
    asm volatile("bar.sync 2, 256;" ::: "memory");
    // scatter: write cell-sorted coordinate copies
    for (int i = ctid; i < NPTS; i += 256){
      float x = s_px[i], y = s_py[i], z = s_pz[i];
      int c = (cellco(z)*GC + cellco(y))*GC + cellco(x);
      unsigned old = atomicAdd(&s_u.grid.cntc[c>>1], (c&1) ? 0x10000u : 1u);
      int pos = (c&1) ? (int)((old >> 16) & 0xFFFFu) : (int)(old & 0xFFFFu);
      s_cpx[pos] = x; s_cpy[pos] = y; s_cpz[pos] = z;
    }
    asm volatile("bar.sync 2, 256;" ::: "memory");
    if (ctid == 0){ __threadfence_block(); *(volatile int*)&s_gridok = 1; }
  }

  // ======== Stage 2: kNN1 + f1 — dynamic queue, grid-pruned, sorted coords =
  {
    while (*(volatile int*)&s_gridok == 0) __nanosleep(128);
    __threadfence_block();
    const float r1sq = 0.09f;
    const float RE = 0.3000003f;      // slack vs fp-marginal radius hits
    for (;;){
      int q;
      if (lane == 0) q = atomicAdd(&s_qhead, 1);
      q = __shfl_sync(FULLM, q, 0);
      if (q >= M1) break;
      while (*(volatile int*)&s_prog < q + 1) __nanosleep(128);
      __threadfence_block();
      const float sx = s_samp[q].x, sy = s_samp[q].y, sz = s_samp[q].z;
      const int lox = cellco(sx - RE), hix = cellco(sx + RE);
      const int loy = cellco(sy - RE), hiy = cellco(sy + RE);
      const int loz = cellco(sz - RE), hiz = cellco(sz + RE);

#define SEG_LOOP(BODY)                                                   \
      for (int zz = loz; zz <= hiz; zz++)                                \
        for (int yy = loy; yy <= hiy; yy++){                             \
          int cb = (zz*GC + yy)*GC;                                      \
          int j0 = (int)s_u.grid.start[cb + lox];                        \
          int j1 = (int)s_u.grid.start[cb + hix + 1];                    \
          for (int j = j0 + lane; j < j1; j += 32){                      \
            float dx = s_cpx[j]-sx, dy = s_cpy[j]-sy, dz = s_cpz[j]-sz;  \
            float d  = fmaf(dz, dz, fmaf(dy, dy, dx*dx));                \
            BODY                                                         \
          }                                                              \
        }

      int cnt = 0;
      int i0 = 0, i1 = 0, i2 = 0, i3 = 0;   // sorted positions of hits
      SEG_LOOP(
        if (d <= r1sq){
          cnt++;
          i0 = (cnt==1)?j:i0; i1 = (cnt==2)?j:i1;
          i2 = (cnt==3)?j:i2; i3 = (cnt==4)?j:i3;
        }
      )
      int tot = isum_xor(cnt);
      float f[F1];
      #pragma unroll
      for (int jj = 0; jj < F1; jj++) f[jj] = 0.0f;

      if (tot <= K1){
        // common: features from <=4 saved candidate positions per lane
        int ii[4] = {i0, i1, i2, i3};
        #pragma unroll
        for (int ss = 0; ss < 4; ss++){
          if (cnt > ss){
            int jj2 = ii[ss];
            float dx = s_cpx[jj2]-sx, dy = s_cpy[jj2]-sy, dz = s_cpz[jj2]-sz;
            #pragma unroll
            for (int jj = 0; jj < F1; jj++){
              float h = dx*s_W1s[jj] + dy*s_W1s[F1+jj] + dz*s_W1s[2*F1+jj] + s_b1[jj];
              f[jj] = fmaxf(f[jj], fmaxf(h, 0.0f));
            }
          }
        }
      } else {
        // rare: K1-th smallest distance as threshold, then segment rescan
        float t;
        if (!__any_sync(FULLM, cnt > 4)){
          float c0 = 3.0e38f, c1v = 3.0e38f, c2v = 3.0e38f, c3v = 3.0e38f;
          if (cnt > 0){ float dx=s_cpx[i0]-sx, dy=s_cpy[i0]-sy, dz=s_cpz[i0]-sz; c0 = fmaf(dz,dz,fmaf(dy,dy,dx*dx)); }
          if (cnt > 1){ float dx=s_cpx[i1]-sx, dy=s_cpy[i1]-sy, dz=s_cpz[i1]-sz; c1v= fmaf(dz,dz,fmaf(dy,dy,dx*dx)); }
          if (cnt > 2){ float dx=s_cpx[i2]-sx, dy=s_cpy[i2]-sy, dz=s_cpz[i2]-sz; c2v= fmaf(dz,dz,fmaf(dy,dy,dx*dx)); }
          if (cnt > 3){ float dx=s_cpx[i3]-sx, dy=s_cpy[i3]-sy, dz=s_cpz[i3]-sz; c3v= fmaf(dz,dz,fmaf(dy,dy,dx*dx)); }
          float prev = -1.0f;
          for (int k = 0; k < K1; k++){
            float mn = 3.0e38f;
            if (c0  > prev) mn = fminf(mn, c0);
            if (c1v > prev) mn = fminf(mn, c1v);
            if (c2v > prev) mn = fminf(mn, c2v);
            if (c3v > prev) mn = fminf(mn, c3v);
            prev = fmin_xor(mn);
          }
          t = prev;
        } else {
          // per-lane overflow (very rare): iterated min over segment scans
          float prev = -1.0f;
          for (int k = 0; k < K1; k++){
            float mn = 3.0e38f;
            SEG_LOOP( if (d > prev && d < mn) mn = d; )
            prev = fmin_xor(mn);
          }
          t = prev;
        }
        SEG_LOOP(
          if (d <= t){
            #pragma unroll
            for (int jj = 0; jj < F1; jj++){
              float h = dx*s_W1s[jj] + dy*s_W1s[F1+jj] + dz*s_W1s[2*F1+jj] + s_b1[jj];
              f[jj] = fmaxf(f[jj], fmaxf(h, 0.0f));
            }
          }
        )
      }
#undef SEG_LOOP
      #pragma unroll
      for (int jj = 0; jj < F1; jj++){
        float v = fredux_max_nn(f[jj]);
        if (lane == 0) s_f1[q][jj] = v;
      }
    }
  }
  __syncthreads();

  // ======== Stage 4: kNN2 + f2 (warps 0..4), register-resident ========
  if (wid < M2){
    const int q = wid;
    const float r2sq = 1.0f;
    const float sx = s_s2x[q], sy = s_s2y[q], sz = s_s2z[q];
    float dd[4]; bool val[4];
    int cnt = 0;
    #pragma unroll
    for (int u = 0; u < 4; u++){
      int i = lane + 32*u;
      val[u] = (i < M1);
      float4 p = s_samp[val[u] ? i : 0];
      float dx = p.x-sx, dy = p.y-sy, dz = p.z-sz;
      dd[u] = dx*dx + dy*dy + dz*dz;
      if (val[u] && dd[u] <= r2sq) cnt++;
    }
    cnt = isum_xor(cnt);
    float t = r2sq;
    if (cnt > K2){
      float prev = -1.0f;
      for (int k = 0; k < K2; k++){
        float mn = 3.0e38f;
        #pragma unroll
        for (int u = 0; u < 4; u++)
          if (val[u] && dd[u] > prev && dd[u] < mn) mn = dd[u];
        prev = fmin_xor(mn);
      }
      t = prev;
    }
    float f[F2];
    #pragma unroll
    for (int j = 0; j < F2; j++) f[j] = 0.0f;
    #pragma unroll
    for (int u = 0; u < 4; u++){
      if (val[u] && dd[u] <= t){
        int i = lane + 32*u;
        float4 p = s_samp[i];
        float dx = p.x-sx, dy = p.y-sy, dz = p.z-sz;
        float g0 = s_f1[i][0], g1 = s_f1[i][1], g2 = s_f1[i][2],
              g3 = s_f1[i][3], g4 = s_f1[i][4];
        #pragma unroll
        for (int j = 0; j < F2; j++){
          float h = s_b2[j]
                  + dx*s_W2[0*F2+j] + dy*s_W2[1*F2+j] + dz*s_W2[2*F2+j]
                  + g0*s_W2[3*F2+j] + g1*s_W2[4*F2+j] + g2*s_W2[5*F2+j]
                  + g3*s_W2[6*F2+j] + g4*s_W2[7*F2+j];
          f[j] = fmaxf(f[j], fmaxf(h, 0.0f));
        }
      }
    }
    #pragma unroll
    for (int j = 0; j < F2; j++){
      float v = fredux_max_nn(f[j]);
      if (lane == 0) s_u.tail.f2[q][j] = v;
    }
  }
  __syncthreads();

  // ---- Stage 5: h3 + latent ----
  if (tid < F3){
    float mx = -3.0e38f;
    for (int i = 0; i < M2; i++){
      float h = b3[tid];
      h += (s_s2x[i]*0.5f) * W3[0*F3+tid];
      h += (s_s2y[i]*0.5f) * W3[1*F3+tid];
      h += (s_s2z[i]*0.5f) * W3[2*F3+tid];
      #pragma unroll 5
      for (int c = 0; c < F2; c++)
        h += s_u.tail.f2[i][c] * W3[(3+c)*F3+tid];
      h = h > 0.0f ? h : 0.0f;
      mx = fmaxf(mx, h);
    }
    s_u.tail.latent[tid] = mx;
  }
  __syncthreads();

  // ---- Stage 6: o1 = latent @ D1 + bD1 ----
  if (tid < 140){
    float v = bD1[tid];
    #pragma unroll 5
    for (int i = 0; i < F3; i++)
      v += s_u.tail.latent[i] * D1[i*140 + tid];
    s_u.tail.o1[tid] = v;
  }
  __syncthreads();
  if (tid < 125){
    int i = tid / F2, c = tid % F2;
    float v = s_u.tail.o1[i*28 + 3 + c];
    s_u.tail.cf[tid] = v > 0.0f ? v : 0.0f;
  }
  __syncthreads();

  // ---- Stage 7: o2 = cf @ D2 + bD2 ----
  for (int t = tid; t < 800; t += NT){
    int i = t / 160, j = t % 160;
    float v = bD2[j];
    #pragma unroll 5
    for (int c = 0; c < F2; c++)
      v += s_u.tail.cf[i*F2 + c] * D2[c*160 + j];
    s_u.tail.o2[t] = v;
  }
  __syncthreads();

  // ---- Stage 8: dec3 + folding combine, per output point ----
  {
    float* O = out + (size_t)b * NPTS * 3;
    for (int g = tid; g < NPTS; g += NT){
      int i2  = g / 400;
      int j20 = g % 20;
      int j8  = (g / 20) % 20;
      const float* o2row = &s_u.tail.o2[i2*160 + j8*8];
      float cf2[F1];
      #pragma unroll
      for (int f = 0; f < F1; f++)
        cf2[f] = fmaxf(o2row[3+f], 0.0f);
      #pragma unroll
      for (int c = 0; c < 3; c++){
        float acc = bD3[j20*3 + c];
        #pragma unroll
        for (int f = 0; f < F1; f++)
          acc = fmaf(cf2[f], D3[f*60 + j20*3 + c], acc);
        float dec  = s_u.tail.o1[i2*28 + c];
        float dec2 = o2row[c];
        O[3*g + c] = ((dec*2.0f + dec2) + acc) * 0.3f;
      }
    }
  }
}

extern "C" void kernel_launch(void* const* d_in, const int* in_sizes, int n_in,
                              void* d_out, int out_size)
{
  cudaFuncSetAttribute(net_kernel,
                       cudaFuncAttributeMaxDynamicSharedMemorySize, DYN_SMEM);
  net_kernel<<<NB, NT, DYN_SMEM>>>(
      (const float*)d_in[0],
      (const float*)d_in[1],  (const float*)d_in[2],
      (const float*)d_in[3],  (const float*)d_in[4],
      (const float*)d_in[5],  (const float*)d_in[6],
      (const float*)d_in[7],  (const float*)d_in[8],
      (const float*)d_in[9],  (const float*)d_in[10],
      (const float*)d_in[11], (const float*)d_in[12],
      (float*)d_out);
}

// round 16
// speedup vs baseline: 1.2855x; 1.2855x over previous
#include <cuda_runtime.h>

#define NB   256
#define NPTS 2000
#define M1   100
#define M2   5
#define K1   20
#define K2   20
#define F1   5
#define F2   25
#define F3   45
#define NT   512
#define FULLM 0xffffffffu

// grid: 14^3 cells of size 0.6 covering [-4.2, 4.2] (clamped outside)
#define GC    14
#define GC2   (GC*GC)
#define GCELLS (GC*GC*GC)          // 2744
#define GPAIRS ((GCELLS+1)/2)      // 1372

#define DYN_SMEM (3*2048*4)        // s_cpx/s_cpy/s_cpz

typedef unsigned long long u64;

// ---- f32x2 packed helpers (rn, bit-identical to scalar FADD/FMUL/FFMA) ----
__device__ __forceinline__ u64 pk2(float a, float b){
  u64 r; asm("mov.b64 %0, {%1,%2};" : "=l"(r) : "f"(a), "f"(b)); return r;
}
__device__ __forceinline__ void upk2(u64 v, float& a, float& b){
  asm("mov.b64 {%0,%1}, %2;" : "=f"(a), "=f"(b) : "l"(v));
}
__device__ __forceinline__ u64 add2(u64 a, u64 b){
  u64 r; asm("add.rn.f32x2 %0, %1, %2;" : "=l"(r) : "l"(a), "l"(b)); return r;
}
__device__ __forceinline__ u64 mul2(u64 a, u64 b){
  u64 r; asm("mul.rn.f32x2 %0, %1, %2;" : "=l"(r) : "l"(a), "l"(b)); return r;
}
__device__ __forceinline__ u64 fma2(u64 a, u64 b, u64 c){
  u64 r; asm("fma.rn.f32x2 %0, %1, %2, %3;" : "=l"(r) : "l"(a), "l"(b), "l"(c)); return r;
}

__device__ __forceinline__ float fmin_xor(float v){
  #pragma unroll
  for (int off = 16; off; off >>= 1)
    v = fminf(v, __shfl_xor_sync(FULLM, v, off));
  return v;
}
__device__ __forceinline__ int isum_xor(int v){
  #pragma unroll
  for (int off = 16; off; off >>= 1)
    v += __shfl_xor_sync(FULLM, v, off);
  return v;
}
__device__ __forceinline__ void argmax_xor(float& v, int& i){
  #pragma unroll
  for (int off = 16; off; off >>= 1){
    float ov = __shfl_xor_sync(FULLM, v, off);
    int   oi = __shfl_xor_sync(FULLM, i, off);
    if (ov > v || (ov == v && oi < i)) { v = ov; i = oi; }
  }
}
__device__ __forceinline__ float fredux_max_nn(float v){
  return __uint_as_float(__reduce_max_sync(FULLM, __float_as_uint(v)));
}
__device__ __forceinline__ int cellco(float x){
  int c = (int)floorf((x + 4.2f) * (1.0f/0.6f));
  return min(GC-1, max(0, c));
}

__global__ void __launch_bounds__(NT, 2)
net_kernel(const float* __restrict__ points,
           const float* __restrict__ W1, const float* __restrict__ b1,
           const float* __restrict__ W2, const float* __restrict__ b2,
           const float* __restrict__ W3, const float* __restrict__ b3,
           const float* __restrict__ D1, const float* __restrict__ bD1,
           const float* __restrict__ D2, const float* __restrict__ bD2,
           const float* __restrict__ D3, const float* __restrict__ bD3,
           float* __restrict__ out)
{
  __shared__ float s_px[NPTS], s_py[NPTS], s_pz[NPTS];   // original order (FPS ties!)
  __shared__ union {
    struct { unsigned cntc[GPAIRS];                      // packed u16 counts/cursors
             unsigned short start[GCELLS+1]; } grid;     // segment starts
    struct { float o1[140]; float cf[125]; float o2[800];
             float latent[F3]; float f2[M2][F2]; } tail;
  } s_u;
  __shared__ float4   s_samp[M1];
  __shared__ float    s_f1[M1][F1];
  __shared__ unsigned s_candv[2][8];
  __shared__ unsigned s_candi[2][8];
  __shared__ int      s_wsum[8];
  __shared__ float    s_s2x[M2], s_s2y[M2], s_s2z[M2];
  __shared__ int      s_s2i[M2];
  __shared__ float    s_W1s[15], s_b1[F1];   // W1 prescaled by 1/R1
  __shared__ float    s_W2[200], s_b2[F2];
  __shared__ int      s_prog, s_qhead, s_gridok;

  // cell-sorted coordinate copies (dynamic smem)
  extern __shared__ float s_dyn[];
  float* s_cpx = s_dyn;
  float* s_cpy = s_dyn + 2048;
  float* s_cpz = s_dyn + 4096;

  const int b = blockIdx.x, tid = threadIdx.x;
  const int lane = tid & 31, wid = tid >> 5;
  const float* P = points + (size_t)b * NPTS * 3;

  // ---- Stage 0: load cloud + small weights ----
  for (int i = tid; i < NPTS; i += NT){
    s_px[i] = P[3*i+0]; s_py[i] = P[3*i+1]; s_pz[i] = P[3*i+2];
  }
  if (tid == 0){ s_prog = 0; s_qhead = 0; s_gridok = 0; }
  if (tid >= 448 && tid < 463)       s_W1s[tid-448] = W1[tid-448] * (1.0f/0.3f);
  if (tid >= 464 && tid < 464+F1)    s_b1[tid-464]  = b1[tid-464];
  if (tid >= 64  && tid < 264)       s_W2[tid-64]   = W2[tid-64];
  if (tid >= 288 && tid < 288+F2)    s_b2[tid-288]  = b2[tid-288];
  __syncthreads();

  if (tid < 256){
    // ======== Producers: FPS level 1 (warps 0-7), f32x2 packed ========
    float md[8];
    u64 pxp[4], pyp[4], pzp[4];
    #pragma unroll
    for (int u2 = 0; u2 < 4; u2++){
      int ia = tid + 256*(2*u2), ib = tid + 256*(2*u2+1);
      int ja = (ia < NPTS) ? ia : 0, jb = (ib < NPTS) ? ib : 0;
      pxp[u2] = pk2(s_px[ja], s_px[jb]);
      pyp[u2] = pk2(s_py[ja], s_py[jb]);
      pzp[u2] = pk2(s_pz[ja], s_pz[jb]);
      md[2*u2]   = (ia < NPTS) ? 1e10f : -1.0f;
      md[2*u2+1] = (ib < NPTS) ? 1e10f : -1.0f;
    }
    int last = 0;
    for (int s = 0; s < M1; s++){
      float lx = s_px[last], ly = s_py[last], lz = s_pz[last];
      if (tid == 0){
        s_samp[s] = make_float4(lx, ly, lz, 0.0f);
        __threadfence_block();
        *(volatile int*)&s_prog = s + 1;
      }
      if (s == M1-1) break;
      u64 nLx = pk2(-lx, -lx), nLy = pk2(-ly, -ly), nLz = pk2(-lz, -lz);
      float bv = -0.5f; int bi = 0;
      #pragma unroll
      for (int u2 = 0; u2 < 4; u2++){
        u64 dx = add2(pxp[u2], nLx);
        u64 dy = add2(pyp[u2], nLy);
        u64 dz = add2(pzp[u2], nLz);
        u64 dd = mul2(dx, dx);
        dd = fma2(dy, dy, dd);
        dd = fma2(dz, dz, dd);
        float d0, d1; upk2(dd, d0, d1);
        int u = 2*u2;
        md[u] = fminf(md[u], d0);
        if (md[u] > bv){ bv = md[u]; bi = tid + 256*u; }
        md[u+1] = fminf(md[u+1], d1);
        if (md[u+1] > bv){ bv = md[u+1]; bi = tid + 256*(u+1); }
      }
      // per-warp argmax (bv >= 0): max on bits, min-index tie-break
      unsigned bits = __float_as_uint(bv);
      unsigned bu = __reduce_max_sync(FULLM, bits);
      unsigned mi = __reduce_min_sync(FULLM, (bits == bu) ? (unsigned)bi : 0xFFFFFFFFu);
      if (lane == 0){ s_candv[s & 1][wid] = bu; s_candi[s & 1][wid] = mi; }
      asm volatile("bar.sync 1, 256;" ::: "memory");
      unsigned cv = (lane < 8) ? s_candv[s & 1][lane] : 0u;
      unsigned ci = (lane < 8) ? s_candi[s & 1][lane] : 0xFFFFFFFFu;
      unsigned gv = __reduce_max_sync(FULLM, cv);
      unsigned gi = __reduce_min_sync(FULLM, (cv == gv) ? ci : 0xFFFFFFFFu);
      last = (int)gi;
    }
    __syncwarp();
    // ---- FPS level 2 (100 -> 5): warp 0 only ----
    if (wid == 0){
      float m[4];
      #pragma unroll
      for (int u = 0; u < 4; u++) m[u] = 1e10f;
      int last2 = 0;
      for (int s = 0; s < M2; s++){
        if (lane == 0) s_s2i[s] = last2;
        const float4 L = s_samp[last2];
        float bv = -1.0f; int bi = 0;
        #pragma unroll
        for (int u = 0; u < 4; u++){
          int i = lane + 32*u;
          if (i < M1){
            float4 p = s_samp[i];
            float dx = p.x-L.x, dy = p.y-L.y, dz = p.z-L.z;
            float d  = dx*dx + dy*dy + dz*dz;
            if (d < m[u]) m[u] = d;
            if (m[u] > bv){ bv = m[u]; bi = i; }
          }
        }
        argmax_xor(bv, bi);
        last2 = __shfl_sync(FULLM, bi, 0);
      }
      __syncwarp();
      if (lane < M2){
        float4 p = s_samp[s_s2i[lane]];
        s_s2x[lane] = p.x; s_s2y[lane] = p.y; s_s2z[lane] = p.z;
      }
    }
  } else {
    // ======== Consumers (warps 8-15): build spatial grid ========
    const int ctid = tid - 256;
    const int cw = ctid >> 5;
    for (int p = ctid; p < GPAIRS; p += 256) s_u.grid.cntc[p] = 0;
    asm volatile("bar.sync 2, 256;" ::: "memory");
    // count
    for (int i = ctid; i < NPTS; i += 256){
      int c = (cellco(s_pz[i])*GC + cellco(s_py[i]))*GC + cellco(s_px[i]);
      atomicAdd(&s_u.grid.cntc[c>>1], (c&1) ? 0x10000u : 1u);
    }
    asm volatile("bar.sync 2, 256;" ::: "memory");
    // prefix sum (each thread owns 11 cells)
    {
      int base = ctid * 11;
      int lc[11]; int sum = 0;
      #pragma unroll
      for (int k = 0; k < 11; k++){
        int c = base + k;
        int v = (c < GCELLS) ? (int)((s_u.grid.cntc[c>>1] >> ((c&1)*16)) & 0xFFFFu) : 0;
        lc[k] = v; sum += v;
      }
      int incl = sum;
      #pragma unroll
      for (int o = 1; o < 32; o <<= 1){
        int n = __shfl_up_sync(FULLM, incl, o);
        if (lane >= o) incl += n;
      }
      if (lane == 31) s_wsum[cw] = incl;
      asm volatile("bar.sync 2, 256;" ::: "memory");
      int woff = 0;
      #pragma unroll
      for (int w = 0; w < 8; w++) woff += (w < cw) ? s_wsum[w] : 0;
      int run = woff + incl - sum;
      #pragma unroll
      for (int k = 0; k < 11; k++){
        int c = base + k;
        if (c <= GCELLS) s_u.grid.start[c] = (unsigned short)run;
        run += lc[k];
      }
    }
    asm volatile("bar.sync 2, 256;" ::: "memory");
    // cursors = copy of starts (reuse cntc)
    for (int p = ctid; p < GPAIRS; p += 256){
      unsigned lo = s_u.grid.start[2*p];
      unsigned hi = s_u.grid.start[2*p+1];
      s_u.grid.cntc[p] = lo | (hi << 16);
    }
    asm volatile("bar.sync 2, 256;" ::: "memory");
    // scatter: write cell-sorted coordinate copies
    for (int i = ctid; i < NPTS; i += 256){
      float x = s_px[i], y = s_py[i], z = s_pz[i];
      int c = (cellco(z)*GC + cellco(y))*GC + cellco(x);
      unsigned old = atomicAdd(&s_u.grid.cntc[c>>1], (c&1) ? 0x10000u : 1u);
      int pos = (c&1) ? (int)((old >> 16) & 0xFFFFu) : (int)(old & 0xFFFFu);
      s_cpx[pos] = x; s_cpy[pos] = y; s_cpz[pos] = z;
    }
    asm volatile("bar.sync 2, 256;" ::: "memory");
    if (ctid == 0){ __threadfence_block(); *(volatile int*)&s_gridok = 1; }
  }

  // ======== Stage 2: kNN1 + f1 — dynamic queue, grid-pruned, sorted coords =
  {
    while (*(volatile int*)&s_gridok == 0) __nanosleep(128);
    __threadfence_block();
    const float r1sq = 0.09f;
    const float RE = 0.3000003f;      // slack vs fp-marginal radius hits
    for (;;){
      int q;
      if (lane == 0) q = atomicAdd(&s_qhead, 1);
      q = __shfl_sync(FULLM, q, 0);
      if (q >= M1) break;
      while (*(volatile int*)&s_prog < q + 1) __nanosleep(128);
      __threadfence_block();
      const float sx = s_samp[q].x, sy = s_samp[q].y, sz = s_samp[q].z;
      const int lox = cellco(sx - RE), hix = cellco(sx + RE);
      const int loy = cellco(sy - RE), hiy = cellco(sy + RE);
      const int loz = cellco(sz - RE), hiz = cellco(sz + RE);

#define SEG_LOOP(BODY)                                                   \
      for (int zz = loz; zz <= hiz; zz++)                                \
        for (int yy = loy; yy <= hiy; yy++){                             \
          int cb = (zz*GC + yy)*GC;                                      \
          int j0 = (int)s_u.grid.start[cb + lox];                        \
          int j1 = (int)s_u.grid.start[cb + hix + 1];                    \
          for (int j = j0 + lane; j < j1; j += 32){                      \
            float dx = s_cpx[j]-sx, dy = s_cpy[j]-sy, dz = s_cpz[j]-sz;  \
            float d  = fmaf(dz, dz, fmaf(dy, dy, dx*dx));                \
            BODY                                                         \
          }                                                              \
        }

      int cnt = 0;
      int i0 = 0, i1 = 0, i2 = 0, i3 = 0;   // sorted positions of hits
      SEG_LOOP(
        if (d <= r1sq){
          cnt++;
          i0 = (cnt==1)?j:i0; i1 = (cnt==2)?j:i1;
          i2 = (cnt==3)?j:i2; i3 = (cnt==4)?j:i3;
        }
      )
      int tot = isum_xor(cnt);
      float f[F1];
      #pragma unroll
      for (int jj = 0; jj < F1; jj++) f[jj] = 0.0f;

      if (tot <= K1){
        // common: features from <=4 saved candidate positions per lane
        int ii[4] = {i0, i1, i2, i3};
        #pragma unroll
        for (int ss = 0; ss < 4; ss++){
          if (cnt > ss){
            int jj2 = ii[ss];
            float dx = s_cpx[jj2]-sx, dy = s_cpy[jj2]-sy, dz = s_cpz[jj2]-sz;
            #pragma unroll
            for (int jj = 0; jj < F1; jj++){
              float h = dx*s_W1s[jj] + dy*s_W1s[F1+jj] + dz*s_W1s[2*F1+jj] + s_b1[jj];
              f[jj] = fmaxf(f[jj], fmaxf(h, 0.0f));
            }
          }
        }
      } else {
        // rare: K1-th smallest distance as threshold, then segment rescan
        float t;
        if (!__any_sync(FULLM, cnt > 4)){
          float c0 = 3.0e38f, c1v = 3.0e38f, c2v = 3.0e38f, c3v = 3.0e38f;
          if (cnt > 0){ float dx=s_cpx[i0]-sx, dy=s_cpy[i0]-sy, dz=s_cpz[i0]-sz; c0 = fmaf(dz,dz,fmaf(dy,dy,dx*dx)); }
          if (cnt > 1){ float dx=s_cpx[i1]-sx, dy=s_cpy[i1]-sy, dz=s_cpz[i1]-sz; c1v= fmaf(dz,dz,fmaf(dy,dy,dx*dx)); }
          if (cnt > 2){ float dx=s_cpx[i2]-sx, dy=s_cpy[i2]-sy, dz=s_cpz[i2]-sz; c2v= fmaf(dz,dz,fmaf(dy,dy,dx*dx)); }
          if (cnt > 3){ float dx=s_cpx[i3]-sx, dy=s_cpy[i3]-sy, dz=s_cpz[i3]-sz; c3v= fmaf(dz,dz,fmaf(dy,dy,dx*dx)); }
          float prev = -1.0f;
          for (int k = 0; k < K1; k++){
            float mn = 3.0e38f;
            if (c0  > prev) mn = fminf(mn, c0);
            if (c1v > prev) mn = fminf(mn, c1v);
            if (c2v > prev) mn = fminf(mn, c2v);
            if (c3v > prev) mn = fminf(mn, c3v);
            prev = fmin_xor(mn);
          }
          t = prev;
        } else {
          // per-lane overflow (very rare): iterated min over segment scans
          float prev = -1.0f;
          for (int k = 0; k < K1; k++){
            float mn = 3.0e38f;
            SEG_LOOP( if (d > prev && d < mn) mn = d; )
            prev = fmin_xor(mn);
          }
          t = prev;
        }
        SEG_LOOP(
          if (d <= t){
            #pragma unroll
            for (int jj = 0; jj < F1; jj++){
              float h = dx*s_W1s[jj] + dy*s_W1s[F1+jj] + dz*s_W1s[2*F1+jj] + s_b1[jj];
              f[jj] = fmaxf(f[jj], fmaxf(h, 0.0f));
            }
          }
        )
      }
#undef SEG_LOOP
      #pragma unroll
      for (int jj = 0; jj < F1; jj++){
        float v = fredux_max_nn(f[jj]);
        if (lane == 0) s_f1[q][jj] = v;
      }
    }
  }
  __syncthreads();

  // ======== Stage 4: kNN2 + f2 (warps 0..4), register-resident ========
  if (wid < M2){
    const int q = wid;
    const float r2sq = 1.0f;
    const float sx = s_s2x[q], sy = s_s2y[q], sz = s_s2z[q];
    float dd[4]; bool val[4];
    int cnt = 0;
    #pragma unroll
    for (int u = 0; u < 4; u++){
      int i = lane + 32*u;
      val[u] = (i < M1);
      float4 p = s_samp[val[u] ? i : 0];
      float dx = p.x-sx, dy = p.y-sy, dz = p.z-sz;
      dd[u] = dx*dx + dy*dy + dz*dz;
      if (val[u] && dd[u] <= r2sq) cnt++;
    }
    cnt = isum_xor(cnt);
    float t = r2sq;
    if (cnt > K2){
      float prev = -1.0f;
      for (int k = 0; k < K2; k++){
        float mn = 3.0e38f;
        #pragma unroll
        for (int u = 0; u < 4; u++)
          if (val[u] && dd[u] > prev && dd[u] < mn) mn = dd[u];
        prev = fmin_xor(mn);
      }
      t = prev;
    }
    float f[F2];
    #pragma unroll
    for (int j = 0; j < F2; j++) f[j] = 0.0f;
    #pragma unroll
    for (int u = 0; u < 4; u++){
      if (val[u] && dd[u] <= t){
        int i = lane + 32*u;
        float4 p = s_samp[i];
        float dx = p.x-sx, dy = p.y-sy, dz = p.z-sz;
        float g0 = s_f1[i][0], g1 = s_f1[i][1], g2 = s_f1[i][2],
              g3 = s_f1[i][3], g4 = s_f1[i][4];
        #pragma unroll
        for (int j = 0; j < F2; j++){
          float h = s_b2[j]
                  + dx*s_W2[0*F2+j] + dy*s_W2[1*F2+j] + dz*s_W2[2*F2+j]
                  + g0*s_W2[3*F2+j] + g1*s_W2[4*F2+j] + g2*s_W2[5*F2+j]
                  + g3*s_W2[6*F2+j] + g4*s_W2[7*F2+j];
          f[j] = fmaxf(f[j], fmaxf(h, 0.0f));
        }
      }
    }
    #pragma unroll
    for (int j = 0; j < F2; j++){
      float v = fredux_max_nn(f[j]);
      if (lane == 0) s_u.tail.f2[q][j] = v;
    }
  }
  __syncthreads();

  // ---- Stage 5: h3 + latent ----
  if (tid < F3){
    float mx = -3.0e38f;
    for (int i = 0; i < M2; i++){
      float h = b3[tid];
      h += (s_s2x[i]*0.5f) * W3[0*F3+tid];
      h += (s_s2y[i]*0.5f) * W3[1*F3+tid];
      h += (s_s2z[i]*0.5f) * W3[2*F3+tid];
      #pragma unroll 5
      for (int c = 0; c < F2; c++)
        h += s_u.tail.f2[i][c] * W3[(3+c)*F3+tid];
      h = h > 0.0f ? h : 0.0f;
      mx = fmaxf(mx, h);
    }
    s_u.tail.latent[tid] = mx;
  }
  __syncthreads();

  // ---- Stage 6: o1 = latent @ D1 + bD1 ----
  if (tid < 140){
    float v = bD1[tid];
    #pragma unroll 5
    for (int i = 0; i < F3; i++)
      v += s_u.tail.latent[i] * D1[i*140 + tid];
    s_u.tail.o1[tid] = v;
  }
  __syncthreads();
  if (tid < 125){
    int i = tid / F2, c = tid % F2;
    float v = s_u.tail.o1[i*28 + 3 + c];
    s_u.tail.cf[tid] = v > 0.0f ? v : 0.0f;
  }
  __syncthreads();

  // ---- Stage 7: o2 = cf @ D2 + bD2 ----
  for (int t = tid; t < 800; t += NT){
    int i = t / 160, j = t % 160;
    float v = bD2[j];
    #pragma unroll 5
    for (int c = 0; c < F2; c++)
      v += s_u.tail.cf[i*F2 + c] * D2[c*160 + j];
    s_u.tail.o2[t] = v;
  }
  __syncthreads();

  // ---- Stage 8: dec3 + folding combine, per output point ----
  {
    float* O = out + (size_t)b * NPTS * 3;
    for (int g = tid; g < NPTS; g += NT){
      int i2  = g / 400;
      int j20 = g % 20;
      int j8  = (g / 20) % 20;
      const float* o2row = &s_u.tail.o2[i2*160 + j8*8];
      float cf2[F1];
      #pragma unroll
      for (int f = 0; f < F1; f++)
        cf2[f] = fmaxf(o2row[3+f], 0.0f);
      #pragma unroll
      for (int c = 0; c < 3; c++){
        float acc = bD3[j20*3 + c];
        #pragma unroll
        for (int f = 0; f < F1; f++)
          acc = fmaf(cf2[f], D3[f*60 + j20*3 + c], acc);
        float dec  = s_u.tail.o1[i2*28 + c];
        float dec2 = o2row[c];
        O[3*g + c] = ((dec*2.0f + dec2) + acc) * 0.3f;
      }
    }
  }
}

extern "C" void kernel_launch(void* const* d_in, const int* in_sizes, int n_in,
                              void* d_out, int out_size)
{
  cudaFuncSetAttribute(net_kernel,
                       cudaFuncAttributeMaxDynamicSharedMemorySize, DYN_SMEM);
  net_kernel<<<NB, NT, DYN_SMEM>>>(
      (const float*)d_in[0],
      (const float*)d_in[1],  (const float*)d_in[2],
      (const float*)d_in[3],  (const float*)d_in[4],
      (const float*)d_in[5],  (const float*)d_in[6],
      (const float*)d_in[7],  (const float*)d_in[8],
      (const float*)d_in[9],  (const float*)d_in[10],
      (const float*)d_in[11], (const float*)d_in[12],
      (float*)d_out);
}

// round 17
// speedup vs baseline: 1.3271x; 1.0324x over previous
#include <cuda_runtime.h>

#define NB   256
#define NPTS 2000
#define M1   100
#define M2   5
#define K1   20
#define K2   20
#define F1   5
#define F2   25
#define F3   45
#define NT   384
#define FULLM 0xffffffffu

// grid: 14^3 cells of size 0.6 covering [-4.2, 4.2] (clamped outside)
#define GC    14
#define GC2   (GC*GC)
#define GCELLS (GC*GC*GC)          // 2744
#define GPAIRS ((GCELLS+1)/2)      // 1372

#define DYN_SMEM (3*2048*4)        // s_cpx/s_cpy/s_cpz

typedef unsigned long long u64;

// ---- f32x2 packed helpers (rn, bit-identical to scalar FADD/FMUL/FFMA) ----
__device__ __forceinline__ u64 pk2(float a, float b){
  u64 r; asm("mov.b64 %0, {%1,%2};" : "=l"(r) : "f"(a), "f"(b)); return r;
}
__device__ __forceinline__ void upk2(u64 v, float& a, float& b){
  asm("mov.b64 {%0,%1}, %2;" : "=f"(a), "=f"(b) : "l"(v));
}
__device__ __forceinline__ u64 add2(u64 a, u64 b){
  u64 r; asm("add.rn.f32x2 %0, %1, %2;" : "=l"(r) : "l"(a), "l"(b)); return r;
}
__device__ __forceinline__ u64 mul2(u64 a, u64 b){
  u64 r; asm("mul.rn.f32x2 %0, %1, %2;" : "=l"(r) : "l"(a), "l"(b)); return r;
}
__device__ __forceinline__ u64 fma2(u64 a, u64 b, u64 c){
  u64 r; asm("fma.rn.f32x2 %0, %1, %2, %3;" : "=l"(r) : "l"(a), "l"(b), "l"(c)); return r;
}

__device__ __forceinline__ float fmin_xor(float v){
  #pragma unroll
  for (int off = 16; off; off >>= 1)
    v = fminf(v, __shfl_xor_sync(FULLM, v, off));
  return v;
}
__device__ __forceinline__ int isum_xor(int v){
  #pragma unroll
  for (int off = 16; off; off >>= 1)
    v += __shfl_xor_sync(FULLM, v, off);
  return v;
}
__device__ __forceinline__ void argmax_xor(float& v, int& i){
  #pragma unroll
  for (int off = 16; off; off >>= 1){
    float ov = __shfl_xor_sync(FULLM, v, off);
    int   oi = __shfl_xor_sync(FULLM, i, off);
    if (ov > v || (ov == v && oi < i)) { v = ov; i = oi; }
  }
}
__device__ __forceinline__ float fredux_max_nn(float v){
  return __uint_as_float(__reduce_max_sync(FULLM, __float_as_uint(v)));
}
__device__ __forceinline__ int cellco(float x){
  int c = (int)floorf((x + 4.2f) * (1.0f/0.6f));
  return min(GC-1, max(0, c));
}

__global__ void __launch_bounds__(NT, 2)
net_kernel(const float* __restrict__ points,
           const float* __restrict__ W1, const float* __restrict__ b1,
           const float* __restrict__ W2, const float* __restrict__ b2,
           const float* __restrict__ W3, const float* __restrict__ b3,
           const float* __restrict__ D1, const float* __restrict__ bD1,
           const float* __restrict__ D2, const float* __restrict__ bD2,
           const float* __restrict__ D3, const float* __restrict__ bD3,
           float* __restrict__ out)
{
  __shared__ float s_px[NPTS], s_py[NPTS], s_pz[NPTS];   // original order (FPS ties!)
  __shared__ union {
    struct { unsigned cntc[GPAIRS];                      // packed u16 counts/cursors
             unsigned short start[GCELLS+1]; } grid;     // segment starts
    struct { float o1[140]; float cf[125]; float o2[800];
             float latent[F3]; float f2[M2][F2]; } tail;
  } s_u;
  __shared__ float4   s_samp[M1];
  __shared__ float    s_f1[M1][F1];
  __shared__ unsigned s_candv[2][8];
  __shared__ unsigned s_candi[2][8];
  __shared__ int      s_wsum[4];
  __shared__ float    s_s2x[M2], s_s2y[M2], s_s2z[M2];
  __shared__ int      s_s2i[M2];
  __shared__ float    s_W1s[15], s_b1[F1];   // W1 prescaled by 1/R1
  __shared__ float    s_W2[200], s_b2[F2];
  __shared__ int      s_prog, s_qhead, s_gridok;

  // cell-sorted coordinate copies (dynamic smem)
  extern __shared__ float s_dyn[];
  float* s_cpx = s_dyn;
  float* s_cpy = s_dyn + 2048;
  float* s_cpz = s_dyn + 4096;

  const int b = blockIdx.x, tid = threadIdx.x;
  const int lane = tid & 31, wid = tid >> 5;
  const float* P = points + (size_t)b * NPTS * 3;

  // ---- Stage 0: load cloud + small weights ----
  for (int i = tid; i < NPTS; i += NT){
    s_px[i] = P[3*i+0]; s_py[i] = P[3*i+1]; s_pz[i] = P[3*i+2];
  }
  if (tid == 0){ s_prog = 0; s_qhead = 0; s_gridok = 0; }
  if (tid >= 320 && tid < 335)       s_W1s[tid-320] = W1[tid-320] * (1.0f/0.3f);
  if (tid >= 336 && tid < 336+F1)    s_b1[tid-336]  = b1[tid-336];
  if (tid >= 64  && tid < 264)       s_W2[tid-64]   = W2[tid-64];
  if (tid >= 288 && tid < 288+F2)    s_b2[tid-288]  = b2[tid-288];
  __syncthreads();

  if (tid < 256){
    // ======== Producers: FPS level 1 (warps 0-7), f32x2 packed ========
    float md[8];
    u64 pxp[4], pyp[4], pzp[4];
    #pragma unroll
    for (int u2 = 0; u2 < 4; u2++){
      int ia = tid + 256*(2*u2), ib = tid + 256*(2*u2+1);
      int ja = (ia < NPTS) ? ia : 0, jb = (ib < NPTS) ? ib : 0;
      pxp[u2] = pk2(s_px[ja], s_px[jb]);
      pyp[u2] = pk2(s_py[ja], s_py[jb]);
      pzp[u2] = pk2(s_pz[ja], s_pz[jb]);
      md[2*u2]   = (ia < NPTS) ? 1e10f : -1.0f;
      md[2*u2+1] = (ib < NPTS) ? 1e10f : -1.0f;
    }
    int last = 0;
    for (int s = 0; s < M1; s++){
      float lx = s_px[last], ly = s_py[last], lz = s_pz[last];
      if (tid == 0){
        s_samp[s] = make_float4(lx, ly, lz, 0.0f);
        __threadfence_block();
        *(volatile int*)&s_prog = s + 1;
      }
      if (s == M1-1) break;
      u64 nLx = pk2(-lx, -lx), nLy = pk2(-ly, -ly), nLz = pk2(-lz, -lz);
      float bv = -0.5f; int bi = 0;
      #pragma unroll
      for (int u2 = 0; u2 < 4; u2++){
        u64 dx = add2(pxp[u2], nLx);
        u64 dy = add2(pyp[u2], nLy);
        u64 dz = add2(pzp[u2], nLz);
        u64 dd = mul2(dx, dx);
        dd = fma2(dy, dy, dd);
        dd = fma2(dz, dz, dd);
        float d0, d1; upk2(dd, d0, d1);
        int u = 2*u2;
        md[u] = fminf(md[u], d0);
        if (md[u] > bv){ bv = md[u]; bi = tid + 256*u; }
        md[u+1] = fminf(md[u+1], d1);
        if (md[u+1] > bv){ bv = md[u+1]; bi = tid + 256*(u+1); }
      }
      // per-warp argmax (bv >= 0): max on bits, min-index tie-break
      unsigned bits = __float_as_uint(bv);
      unsigned bu = __reduce_max_sync(FULLM, bits);
      unsigned mi = __reduce_min_sync(FULLM, (bits == bu) ? (unsigned)bi : 0xFFFFFFFFu);
      if (lane == 0){ s_candv[s & 1][wid] = bu; s_candi[s & 1][wid] = mi; }
      asm volatile("bar.sync 1, 256;" ::: "memory");
      unsigned cv = (lane < 8) ? s_candv[s & 1][lane] : 0u;
      unsigned ci = (lane < 8) ? s_candi[s & 1][lane] : 0xFFFFFFFFu;
      unsigned gv = __reduce_max_sync(FULLM, cv);
      unsigned gi = __reduce_min_sync(FULLM, (cv == gv) ? ci : 0xFFFFFFFFu);
      last = (int)gi;
    }
    __syncwarp();
    // ---- FPS level 2 (100 -> 5): warp 0 only ----
    if (wid == 0){
      float m[4];
      #pragma unroll
      for (int u = 0; u < 4; u++) m[u] = 1e10f;
      int last2 = 0;
      for (int s = 0; s < M2; s++){
        if (lane == 0) s_s2i[s] = last2;
        const float4 L = s_samp[last2];
        float bv = -1.0f; int bi = 0;
        #pragma unroll
        for (int u = 0; u < 4; u++){
          int i = lane + 32*u;
          if (i < M1){
            float4 p = s_samp[i];
            float dx = p.x-L.x, dy = p.y-L.y, dz = p.z-L.z;
            float d  = dx*dx + dy*dy + dz*dz;
            if (d < m[u]) m[u] = d;
            if (m[u] > bv){ bv = m[u]; bi = i; }
          }
        }
        argmax_xor(bv, bi);
        last2 = __shfl_sync(FULLM, bi, 0);
      }
      __syncwarp();
      if (lane < M2){
        float4 p = s_samp[s_s2i[lane]];
        s_s2x[lane] = p.x; s_s2y[lane] = p.y; s_s2z[lane] = p.z;
      }
    }
  } else {
    // ======== Consumers (warps 8-11, 128 threads): build spatial grid ======
    const int ctid = tid - 256;
    const int cw = ctid >> 5;
    for (int p = ctid; p < GPAIRS; p += 128) s_u.grid.cntc[p] = 0;
    asm volatile("bar.sync 2, 128;" ::: "memory");
    // count
    for (int i = ctid; i < NPTS; i += 128){
      int c = (cellco(s_pz[i])*GC + cellco(s_py[i]))*GC + cellco(s_px[i]);
      atomicAdd(&s_u.grid.cntc[c>>1], (c&1) ? 0x10000u : 1u);
    }
    asm volatile("bar.sync 2, 128;" ::: "memory");
    // prefix sum (each thread owns 22 cells)
    {
      int base = ctid * 22;
      int lc[22]; int sum = 0;
      #pragma unroll
      for (int k = 0; k < 22; k++){
        int c = base + k;
        int v = (c < GCELLS) ? (int)((s_u.grid.cntc[c>>1] >> ((c&1)*16)) & 0xFFFFu) : 0;
        lc[k] = v; sum += v;
      }
      int incl = sum;
      #pragma unroll
      for (int o = 1; o < 32; o <<= 1){
        int n = __shfl_up_sync(FULLM, incl, o);
        if (lane >= o) incl += n;
      }
      if (lane == 31) s_wsum[cw] = incl;
      asm volatile("bar.sync 2, 128;" ::: "memory");
      int woff = 0;
      #pragma unroll
      for (int w = 0; w < 4; w++) woff += (w < cw) ? s_wsum[w] : 0;
      int run = woff + incl - sum;
      #pragma unroll
      for (int k = 0; k < 22; k++){
        int c = base + k;
        if (c <= GCELLS) s_u.grid.start[c] = (unsigned short)run;
        run += lc[k];
      }
    }
    asm volatile("bar.sync 2, 128;" ::: "memory");
    // cursors = copy of starts (reuse cntc)
    for (int p = ctid; p < GPAIRS; p += 128){
      unsigned lo = s_u.grid.start[2*p];
      unsigned hi = s_u.grid.start[2*p+1];
      s_u.grid.cntc[p] = lo | (hi << 16);
    }
    asm volatile("bar.sync 2, 128;" ::: "memory");
    // scatter: write cell-sorted coordinate copies
    for (int i = ctid; i < NPTS; i += 128){
      float x = s_px[i], y = s_py[i], z = s_pz[i];
      int c = (cellco(z)*GC + cellco(y))*GC + cellco(x);
      unsigned old = atomicAdd(&s_u.grid.cntc[c>>1], (c&1) ? 0x10000u : 1u);
      int pos = (c&1) ? (int)((old >> 16) & 0xFFFFu) : (int)(old & 0xFFFFu);
      s_cpx[pos] = x; s_cpy[pos] = y; s_cpz[pos] = z;
    }
    asm volatile("bar.sync 2, 128;" ::: "memory");
    if (ctid == 0){ __threadfence_block(); *(volatile int*)&s_gridok = 1; }
  }

  // ======== Stage 2: kNN1 + f1 — dynamic queue, grid-pruned, sorted coords =
  {
    while (*(volatile int*)&s_gridok == 0) __nanosleep(128);
    __threadfence_block();
    const float r1sq = 0.09f;
    const float RE = 0.3000003f;      // slack vs fp-marginal radius hits
    for (;;){
      int q;
      if (lane == 0) q = atomicAdd(&s_qhead, 1);
      q = __shfl_sync(FULLM, q, 0);
      if (q >= M1) break;
      while (*(volatile int*)&s_prog < q + 1) __nanosleep(128);
      __threadfence_block();
      const float sx = s_samp[q].x, sy = s_samp[q].y, sz = s_samp[q].z;
      const int lox = cellco(sx - RE), hix = cellco(sx + RE);
      const int loy = cellco(sy - RE), hiy = cellco(sy + RE);
      const int loz = cellco(sz - RE), hiz = cellco(sz + RE);

#define SEG_LOOP(BODY)                                                   \
      for (int zz = loz; zz <= hiz; zz++)                                \
        for (int yy = loy; yy <= hiy; yy++){                             \
          int cb = (zz*GC + yy)*GC;                                      \
          int j0 = (int)s_u.grid.start[cb + lox];                        \
          int j1 = (int)s_u.grid.start[cb + hix + 1];                    \
          for (int j = j0 + lane; j < j1; j += 32){                      \
            float dx = s_cpx[j]-sx, dy = s_cpy[j]-sy, dz = s_cpz[j]-sz;  \
            float d  = fmaf(dz, dz, fmaf(dy, dy, dx*dx));                \
            BODY                                                         \
          }                                                              \
        }

      int cnt = 0;
      int i0 = 0, i1 = 0, i2 = 0, i3 = 0;   // sorted positions of hits
      SEG_LOOP(
        if (d <= r1sq){
          cnt++;
          i0 = (cnt==1)?j:i0; i1 = (cnt==2)?j:i1;
          i2 = (cnt==3)?j:i2; i3 = (cnt==4)?j:i3;
        }
      )
      int tot = isum_xor(cnt);
      float f[F1];
      #pragma unroll
      for (int jj = 0; jj < F1; jj++) f[jj] = 0.0f;

      if (tot <= K1){
        // common: features from <=4 saved candidate positions per lane
        int ii[4] = {i0, i1, i2, i3};
        #pragma unroll
        for (int ss = 0; ss < 4; ss++){
          if (cnt > ss){
            int jj2 = ii[ss];
            float dx = s_cpx[jj2]-sx, dy = s_cpy[jj2]-sy, dz = s_cpz[jj2]-sz;
            #pragma unroll
            for (int jj = 0; jj < F1; jj++){
              float h = dx*s_W1s[jj] + dy*s_W1s[F1+jj] + dz*s_W1s[2*F1+jj] + s_b1[jj];
              f[jj] = fmaxf(f[jj], fmaxf(h, 0.0f));
            }
          }
        }
      } else {
        // rare: K1-th smallest distance as threshold, then segment rescan
        float t;
        if (!__any_sync(FULLM, cnt > 4)){
          float c0 = 3.0e38f, c1v = 3.0e38f, c2v = 3.0e38f, c3v = 3.0e38f;
          if (cnt > 0){ float dx=s_cpx[i0]-sx, dy=s_cpy[i0]-sy, dz=s_cpz[i0]-sz; c0 = fmaf(dz,dz,fmaf(dy,dy,dx*dx)); }
          if (cnt > 1){ float dx=s_cpx[i1]-sx, dy=s_cpy[i1]-sy, dz=s_cpz[i1]-sz; c1v= fmaf(dz,dz,fmaf(dy,dy,dx*dx)); }
          if (cnt > 2){ float dx=s_cpx[i2]-sx, dy=s_cpy[i2]-sy, dz=s_cpz[i2]-sz; c2v= fmaf(dz,dz,fmaf(dy,dy,dx*dx)); }
          if (cnt > 3){ float dx=s_cpx[i3]-sx, dy=s_cpy[i3]-sy, dz=s_cpz[i3]-sz; c3v= fmaf(dz,dz,fmaf(dy,dy,dx*dx)); }
          float prev = -1.0f;
          for (int k = 0; k < K1; k++){
            float mn = 3.0e38f;
            if (c0  > prev) mn = fminf(mn, c0);
            if (c1v > prev) mn = fminf(mn, c1v);
            if (c2v > prev) mn = fminf(mn, c2v);
            if (c3v > prev) mn = fminf(mn, c3v);
            prev = fmin_xor(mn);
          }
          t = prev;
        } else {
          // per-lane overflow (very rare): iterated min over segment scans
          float prev = -1.0f;
          for (int k = 0; k < K1; k++){
            float mn = 3.0e38f;
            SEG_LOOP( if (d > prev && d < mn) mn = d; )
            prev = fmin_xor(mn);
          }
          t = prev;
        }
        SEG_LOOP(
          if (d <= t){
            #pragma unroll
            for (int jj = 0; jj < F1; jj++){
              float h = dx*s_W1s[jj] + dy*s_W1s[F1+jj] + dz*s_W1s[2*F1+jj] + s_b1[jj];
              f[jj] = fmaxf(f[jj], fmaxf(h, 0.0f));
            }
          }
        )
      }
#undef SEG_LOOP
      #pragma unroll
      for (int jj = 0; jj < F1; jj++){
        float v = fredux_max_nn(f[jj]);
        if (lane == 0) s_f1[q][jj] = v;
      }
    }
  }
  __syncthreads();

  // ======== Stage 4: kNN2 + f2 (warps 0..4), register-resident ========
  if (wid < M2){
    const int q = wid;
    const float r2sq = 1.0f;
    const float sx = s_s2x[q], sy = s_s2y[q], sz = s_s2z[q];
    float dd[4]; bool val[4];
    int cnt = 0;
    #pragma unroll
    for (int u = 0; u < 4; u++){
      int i = lane + 32*u;
      val[u] = (i < M1);
      float4 p = s_samp[val[u] ? i : 0];
      float dx = p.x-sx, dy = p.y-sy, dz = p.z-sz;
      dd[u] = dx*dx + dy*dy + dz*dz;
      if (val[u] && dd[u] <= r2sq) cnt++;
    }
    cnt = isum_xor(cnt);
    float t = r2sq;
    if (cnt > K2){
      float prev = -1.0f;
      for (int k = 0; k < K2; k++){
        float mn = 3.0e38f;
        #pragma unroll
        for (int u = 0; u < 4; u++)
          if (val[u] && dd[u] > prev && dd[u] < mn) mn = dd[u];
        prev = fmin_xor(mn);
      }
      t = prev;
    }
    float f[F2];
    #pragma unroll
    for (int j = 0; j < F2; j++) f[j] = 0.0f;
    #pragma unroll
    for (int u = 0; u < 4; u++){
      if (val[u] && dd[u] <= t){
        int i = lane + 32*u;
        float4 p = s_samp[i];
        float dx = p.x-sx, dy = p.y-sy, dz = p.z-sz;
        float g0 = s_f1[i][0], g1 = s_f1[i][1], g2 = s_f1[i][2],
              g3 = s_f1[i][3], g4 = s_f1[i][4];
        #pragma unroll
        for (int j = 0; j < F2; j++){
          float h = s_b2[j]
                  + dx*s_W2[0*F2+j] + dy*s_W2[1*F2+j] + dz*s_W2[2*F2+j]
                  + g0*s_W2[3*F2+j] + g1*s_W2[4*F2+j] + g2*s_W2[5*F2+j]
                  + g3*s_W2[6*F2+j] + g4*s_W2[7*F2+j];
          f[j] = fmaxf(f[j], fmaxf(h, 0.0f));
        }
      }
    }
    #pragma unroll
    for (int j = 0; j < F2; j++){
      float v = fredux_max_nn(f[j]);
      if (lane == 0) s_u.tail.f2[q][j] = v;
    }
  }
  __syncthreads();

  // ---- Stage 5: h3 + latent ----
  if (tid < F3){
    float mx = -3.0e38f;
    for (int i = 0; i < M2; i++){
      float h = b3[tid];
      h += (s_s2x[i]*0.5f) * W3[0*F3+tid];
      h += (s_s2y[i]*0.5f) * W3[1*F3+tid];
      h += (s_s2z[i]*0.5f) * W3[2*F3+tid];
      #pragma unroll 5
      for (int c = 0; c < F2; c++)
        h += s_u.tail.f2[i][c] * W3[(3+c)*F3+tid];
      h = h > 0.0f ? h : 0.0f;
      mx = fmaxf(mx, h);
    }
    s_u.tail.latent[tid] = mx;
  }
  __syncthreads();

  // ---- Stage 6: o1 = latent @ D1 + bD1 ----
  if (tid < 140){
    float v = bD1[tid];
    #pragma unroll 5
    for (int i = 0; i < F3; i++)
      v += s_u.tail.latent[i] * D1[i*140 + tid];
    s_u.tail.o1[tid] = v;
  }
  __syncthreads();
  if (tid < 125){
    int i = tid / F2, c = tid % F2;
    float v = s_u.tail.o1[i*28 + 3 + c];
    s_u.tail.cf[tid] = v > 0.0f ? v : 0.0f;
  }
  __syncthreads();

  // ---- Stage 7: o2 = cf @ D2 + bD2 ----
  for (int t = tid; t < 800; t += NT){
    int i = t / 160, j = t % 160;
    float v = bD2[j];
    #pragma unroll 5
    for (int c = 0; c < F2; c++)
      v += s_u.tail.cf[i*F2 + c] * D2[c*160 + j];
    s_u.tail.o2[t] = v;
  }
  __syncthreads();

  // ---- Stage 8: dec3 + folding combine, per output point ----
  {
    float* O = out + (size_t)b * NPTS * 3;
    for (int g = tid; g < NPTS; g += NT){
      int i2  = g / 400;
      int j20 = g % 20;
      int j8  = (g / 20) % 20;
      const float* o2row = &s_u.tail.o2[i2*160 + j8*8];
      float cf2[F1];
      #pragma unroll
      for (int f = 0; f < F1; f++)
        cf2[f] = fmaxf(o2row[3+f], 0.0f);
      #pragma unroll
      for (int c = 0; c < 3; c++){
        float acc = bD3[j20*3 + c];
        #pragma unroll
        for (int f = 0; f < F1; f++)
          acc = fmaf(cf2[f], D3[f*60 + j20*3 + c], acc);
        float dec  = s_u.tail.o1[i2*28 + c];
        float dec2 = o2row[c];
        O[3*g + c] = ((dec*2.0f + dec2) + acc) * 0.3f;
      }
    }
  }
}

extern "C" void kernel_launch(void* const* d_in, const int* in_sizes, int n_in,
                              void* d_out, int out_size)
{
  cudaFuncSetAttribute(net_kernel,
                       cudaFuncAttributeMaxDynamicSharedMemorySize, DYN_SMEM);
  net_kernel<<<NB, NT, DYN_SMEM>>>(
      (const float*)d_in[0],
      (const float*)d_in[1],  (const float*)d_in[2],
      (const float*)d_in[3],  (const float*)d_in[4],
      (const float*)d_in[5],  (const float*)d_in[6],
      (const float*)d_in[7],  (const float*)d_in[8],
      (const float*)d_in[9],  (const float*)d_in[10],
      (const float*)d_in[11], (const float*)d_in[12],
      (float*)d_out);
}